// round 5
// baseline (speedup 1.0000x reference)
#include <cuda_runtime.h>
#include <math.h>
#include <stdint.h>

#define Bsz 512
#define Tsz 512
#define Isz 64
#define Hsz 256

// Scratch: two full-sequence buffers (ping-pong between layers).
__device__ float g_seqA[Bsz * Tsz * Hsz];   // 256 MiB
__device__ float g_seqB[Bsz * Tsz * Hsz];   // 256 MiB

__device__ __forceinline__ uint32_t smem_u32(const void* p) {
    uint32_t a;
    asm("{ .reg .u64 t; cvta.to.shared.u64 t, %1; cvt.u32.u64 %0, t; }"
        : "=r"(a) : "l"(p));
    return a;
}

// ---------------------------------------------------------------------------
// Projection GEMM: C[M, Hsz] = X[M, K] @ W[Hsz, K]^T + b1 + b2
// M = B*T = 262144, K = 64 (layer 0) or 256 (layers 1,2)
// ---------------------------------------------------------------------------
#define PBM 128
#define PBN 64
#define PBK 32
#define PTM 8
#define PTN 4

__global__ __launch_bounds__(256) void proj_kernel(
    const float* __restrict__ X, const float* __restrict__ W,
    const float* __restrict__ b1, const float* __restrict__ b2,
    float* __restrict__ C, int K)
{
    __shared__ float Xs[PBK][PBM + 4];
    __shared__ float Ws[PBK][PBN + 4];

    const int tid = threadIdx.x;
    const int tx = tid & 15;
    const int ty = tid >> 4;
    const int m0 = blockIdx.x * PBM;
    const int n0 = blockIdx.y * PBN;

    float acc[PTM][PTN];
#pragma unroll
    for (int i = 0; i < PTM; i++)
#pragma unroll
        for (int j = 0; j < PTN; j++) acc[i][j] = 0.0f;

    for (int kt = 0; kt < K; kt += PBK) {
#pragma unroll
        for (int l = 0; l < 4; l++) {
            int id  = tid + 256 * l;
            int row = id >> 3;
            int kq  = (id & 7) * 4;
            float4 v = *(const float4*)&X[(m0 + row) * K + kt + kq];
            Xs[kq + 0][row] = v.x;
            Xs[kq + 1][row] = v.y;
            Xs[kq + 2][row] = v.z;
            Xs[kq + 3][row] = v.w;
        }
#pragma unroll
        for (int l = 0; l < 2; l++) {
            int id  = tid + 256 * l;
            int row = id >> 3;
            int kq  = (id & 7) * 4;
            float4 v = *(const float4*)&W[(n0 + row) * K + kt + kq];
            Ws[kq + 0][row] = v.x;
            Ws[kq + 1][row] = v.y;
            Ws[kq + 2][row] = v.z;
            Ws[kq + 3][row] = v.w;
        }
        __syncthreads();

#pragma unroll
        for (int k = 0; k < PBK; k++) {
            float a[PTM], w[PTN];
#pragma unroll
            for (int i = 0; i < PTM; i++) a[i] = Xs[k][ty * PTM + i];
#pragma unroll
            for (int j = 0; j < PTN; j++) w[j] = Ws[k][tx * PTN + j];
#pragma unroll
            for (int i = 0; i < PTM; i++)
#pragma unroll
                for (int j = 0; j < PTN; j++)
                    acc[i][j] = fmaf(a[i], w[j], acc[i][j]);
        }
        __syncthreads();
    }

#pragma unroll
    for (int j = 0; j < PTN; j++) {
        int n = n0 + tx * PTN + j;
        float bb = b1[n] + b2[n];
#pragma unroll
        for (int i = 0; i < PTM; i++) {
            C[(m0 + ty * PTM + i) * Hsz + n] = acc[i][j] + bb;
        }
    }
}

// ---------------------------------------------------------------------------
// Recurrence, W_hh register-resident. 2-CTA cluster splits the output dim:
// CTA rank owns j in [rank*128, rank*128+128). 512 threads = 16 warps;
// warp = 8 j-rows x 4 k-slices (k interleaved at 16B granularity so the 4
// slice addresses of one LDS.128 are 64B-contiguous -> 1 wavefront).
// Each lane holds 16 float4 of W (64 regs). Partial dots reduced via
// shfl_xor over the ks lane bits. h exchanged with the peer CTA via DSMEM.
// In-place on seq (pre-activation -> h).
// ---------------------------------------------------------------------------
#define RMC 8            // batch rows per cluster
#define HP  260          // padded h row pitch (floats); 260*4 % 16 == 0

__global__ void __launch_bounds__(512) __cluster_dims__(2, 1, 1)
rec3_kernel(const float* __restrict__ w_hh, float* __restrict__ seq)
{
    __shared__ __align__(16) float hbuf[2][RMC * HP];

    const int tid  = threadIdx.x;
    const int lane = tid & 31;
    const int wi   = tid >> 5;            // warp 0..15
    const int jl   = lane >> 2;           // 0..7
    const int ks   = lane & 3;            // k-slice 0..3
    const unsigned rank = blockIdx.x & 1;
    const int jloc = wi * 8 + jl;         // 0..127
    const int jg   = (int)rank * 128 + jloc;
    const int b0   = (blockIdx.x >> 1) * RMC;
    const int bA   = 2 * ks;              // this lane's 2 publish rows
    const int bB   = 2 * ks + 1;

    // Register-resident W: lane owns row jg, chunks k = 16m + 4ks .. +3
    float4 w4[16];
#pragma unroll
    for (int m = 0; m < 16; m++)
        w4[m] = *(const float4*)&w_hh[jg * Hsz + m * 16 + ks * 4];

    // h_{-1} = 0
    for (int idx = tid; idx < RMC * HP; idx += 512) hbuf[0][idx] = 0.0f;

    // Peer-CTA addresses of the two h buffers
    uint32_t l0 = smem_u32(&hbuf[0][0]), l1 = smem_u32(&hbuf[1][0]);
    uint32_t p0, p1;
    asm("mapa.shared::cluster.u32 %0, %1, %2;" : "=r"(p0) : "r"(l0), "r"(rank ^ 1u));
    asm("mapa.shared::cluster.u32 %0, %1, %2;" : "=r"(p1) : "r"(l1), "r"(rank ^ 1u));

    asm volatile("barrier.cluster.arrive.aligned;" ::: "memory");
    asm volatile("barrier.cluster.wait.aligned;" ::: "memory");

    // Prefetch pre-activations for t = 0 (this lane's 2 rows)
    float nA = seq[((b0 + bA) * Tsz + 0) * Hsz + jg];
    float nB = seq[((b0 + bB) * Tsz + 0) * Hsz + jg];

    for (int t = 0; t < Tsz; t++) {
        const float* hc = hbuf[t & 1];
        float*       hn = hbuf[(t & 1) ^ 1];
        uint32_t     pn = (t & 1) ? p0 : p1;

        float pA = nA, pB = nB;
        // Prefetch next step's pre-activations (hidden behind k-loop)
        if (t + 1 < Tsz) {
            nA = seq[((b0 + bA) * Tsz + t + 1) * Hsz + jg];
            nB = seq[((b0 + bB) * Tsz + t + 1) * Hsz + jg];
        }

        float acc[RMC];
#pragma unroll
        for (int b = 0; b < RMC; b++) acc[b] = 0.0f;

#pragma unroll
        for (int m = 0; m < 16; m++) {
            const int base = m * 16 + ks * 4;
            const float4 w = w4[m];
#pragma unroll
            for (int b = 0; b < RMC; b++) {
                float4 h = *(const float4*)&hc[b * HP + base];
                acc[b] = fmaf(w.x, h.x, acc[b]);
                acc[b] = fmaf(w.y, h.y, acc[b]);
                acc[b] = fmaf(w.z, h.z, acc[b]);
                acc[b] = fmaf(w.w, h.w, acc[b]);
            }
        }

        // Reduce the 4 k-slices (lane bits 0..1)
#pragma unroll
        for (int b = 0; b < RMC; b++) {
            acc[b] += __shfl_xor_sync(0xffffffffu, acc[b], 1);
            acc[b] += __shfl_xor_sync(0xffffffffu, acc[b], 2);
        }

        // This lane finalizes rows bA, bB
        float hA = tanhf(acc[bA] + pA);
        float hB = tanhf(acc[bB] + pB);

        hn[bA * HP + jg] = hA;
        hn[bB * HP + jg] = hB;
        asm volatile("st.shared::cluster.f32 [%0], %1;"
                     :: "r"(pn + (uint32_t)(bA * HP + jg) * 4u), "f"(hA) : "memory");
        asm volatile("st.shared::cluster.f32 [%0], %1;"
                     :: "r"(pn + (uint32_t)(bB * HP + jg) * 4u), "f"(hB) : "memory");
        seq[((b0 + bA) * Tsz + t) * Hsz + jg] = hA;
        seq[((b0 + bB) * Tsz + t) * Hsz + jg] = hB;

        // One cluster barrier per step (release/acquire orders h publishes)
        asm volatile("barrier.cluster.arrive.aligned;" ::: "memory");
        asm volatile("barrier.cluster.wait.aligned;" ::: "memory");
    }
}

// ---------------------------------------------------------------------------
// Final FC: out[b] = h[b, T-1, :] . w_fc + b_fc     (one warp per batch row)
// ---------------------------------------------------------------------------
__global__ __launch_bounds__(256) void fc_kernel(
    const float* __restrict__ seq, const float* __restrict__ wfc,
    const float* __restrict__ bfc, float* __restrict__ out)
{
    int warp = (blockIdx.x * blockDim.x + threadIdx.x) >> 5;
    int lane = threadIdx.x & 31;
    if (warp >= Bsz) return;
    const float* hrow = &seq[(warp * Tsz + (Tsz - 1)) * Hsz];
    float s = 0.0f;
#pragma unroll
    for (int i = lane; i < Hsz; i += 32) s = fmaf(hrow[i], wfc[i], s);
#pragma unroll
    for (int o = 16; o; o >>= 1) s += __shfl_xor_sync(0xffffffffu, s, o);
    if (lane == 0) out[warp] = s + bfc[0];
}

// ---------------------------------------------------------------------------
extern "C" void kernel_launch(void* const* d_in, const int* in_sizes, int n_in,
                              void* d_out, int out_size)
{
    const float* x     = (const float*)d_in[0];
    const float* w_ih0 = (const float*)d_in[1];
    const float* w_hh0 = (const float*)d_in[2];
    const float* b_ih0 = (const float*)d_in[3];
    const float* b_hh0 = (const float*)d_in[4];
    const float* w_ih1 = (const float*)d_in[5];
    const float* w_hh1 = (const float*)d_in[6];
    const float* b_ih1 = (const float*)d_in[7];
    const float* b_hh1 = (const float*)d_in[8];
    const float* w_ih2 = (const float*)d_in[9];
    const float* w_hh2 = (const float*)d_in[10];
    const float* b_ih2 = (const float*)d_in[11];
    const float* b_hh2 = (const float*)d_in[12];
    const float* w_fc  = (const float*)d_in[13];
    const float* b_fc  = (const float*)d_in[14];
    float* out = (float*)d_out;

    float *seqA, *seqB;
    cudaGetSymbolAddress((void**)&seqA, g_seqA);
    cudaGetSymbolAddress((void**)&seqB, g_seqB);

    dim3 pgrid(Bsz * Tsz / PBM, Hsz / PBN);   // (2048, 4)
    const int rec_grid = (Bsz / RMC) * 2;     // 128 CTAs = 64 clusters

    // Layer 0
    proj_kernel<<<pgrid, 256>>>(x, w_ih0, b_ih0, b_hh0, seqA, Isz);
    rec3_kernel<<<rec_grid, 512>>>(w_hh0, seqA);

    // Layer 1
    proj_kernel<<<pgrid, 256>>>(seqA, w_ih1, b_ih1, b_hh1, seqB, Hsz);
    rec3_kernel<<<rec_grid, 512>>>(w_hh1, seqB);

    // Layer 2
    proj_kernel<<<pgrid, 256>>>(seqB, w_ih2, b_ih2, b_hh2, seqA, Hsz);
    rec3_kernel<<<rec_grid, 512>>>(w_hh2, seqA);

    // Head
    fc_kernel<<<(Bsz * 32 + 255) / 256, 256>>>(seqA, w_fc, b_fc, out);
}